// round 6
// baseline (speedup 1.0000x reference)
#include <cuda_runtime.h>
#include <math.h>

#define BATCH 2048
#define STEPS 64
#define HID   64
#define NZv   32
#define INZ   32
#define DOUT  8
#define BT    14
#define NTHR  512
#define NCTA  ((BATCH + BT - 1) / BT)   /* 147 */

// -------- pre-transposed weight scratch (filled by prep_kernel each call) ----
__device__ float4 g_W0P4 [16 * 256];  // [m][o]: Wx0[o][4m+1..4m+4] (x=v for o<128 else c)
__device__ float  g_w0t  [256];       // Wx0[o][0]  (the t column)
__device__ float4 g_W1P4 [32 * 256];  // [m][o]: Wx1[o][4m..4m+3]
__device__ float4 g_Wv2P4[32 * 64];   // [m][o]: Wv2[o][4m..4m+3]
__device__ float  g_Wc2T [128 * 2048];// [k][n]  (n contiguous -> LDG.128 per k)
__device__ float  g_Wi0T [32  * 128];
__device__ float  g_Wi1T [128 * 128];
__device__ float  g_Wi2T [128 * 64];
__device__ float  g_b0   [256];       // [bv0 | bc0]
__device__ float  g_b1   [256];       // [bv1 | bc1]
__device__ float  g_WrT  [64 * 8];    // WrT[h][d]

__global__ void prep_kernel(const float* __restrict__ Wi0, const float* __restrict__ Wi1,
                            const float* __restrict__ Wi2,
                            const float* __restrict__ Wv0, const float* __restrict__ bv0,
                            const float* __restrict__ Wv1, const float* __restrict__ bv1,
                            const float* __restrict__ Wv2,
                            const float* __restrict__ Wc0, const float* __restrict__ bc0,
                            const float* __restrict__ Wc1, const float* __restrict__ bc1,
                            const float* __restrict__ Wc2, const float* __restrict__ Wr) {
    int tid = blockIdx.x * blockDim.x + threadIdx.x;
    int nt  = gridDim.x * blockDim.x;
    for (int i = tid; i < 16 * 256; i += nt) {
        int m = i >> 8, o = i & 255;
        const float* row = (o < 128) ? &Wv0[o * 65] : &Wc0[(o - 128) * 65];
        g_W0P4[i] = make_float4(row[4 * m + 1], row[4 * m + 2], row[4 * m + 3], row[4 * m + 4]);
    }
    for (int o = tid; o < 256; o += nt) {
        const float* row = (o < 128) ? &Wv0[o * 65] : &Wc0[(o - 128) * 65];
        g_w0t[o] = row[0];
        g_b0[o] = (o < 128) ? bv0[o] : bc0[o - 128];
        g_b1[o] = (o < 128) ? bv1[o] : bc1[o - 128];
    }
    for (int i = tid; i < 32 * 256; i += nt) {
        int m = i >> 8, o = i & 255;
        const float* row = (o < 128) ? &Wv1[o * 128] : &Wc1[(o - 128) * 128];
        g_W1P4[i] = make_float4(row[4 * m], row[4 * m + 1], row[4 * m + 2], row[4 * m + 3]);
    }
    for (int i = tid; i < 32 * 64; i += nt) {
        int m = i >> 6, o = i & 63;
        const float* row = &Wv2[o * 128];
        g_Wv2P4[i] = make_float4(row[4 * m], row[4 * m + 1], row[4 * m + 2], row[4 * m + 3]);
    }
    for (int i = tid; i < 128 * 2048; i += nt) {
        int k = i >> 11, n = i & 2047;
        g_Wc2T[i] = Wc2[n * 128 + k];
    }
    for (int i = tid; i < 32 * 128; i += nt) {
        int k = i >> 7, o = i & 127;
        g_Wi0T[i] = Wi0[o * 32 + k];
    }
    for (int i = tid; i < 128 * 128; i += nt) {
        int k = i >> 7, o = i & 127;
        g_Wi1T[i] = Wi1[o * 128 + k];
    }
    for (int i = tid; i < 128 * 64; i += nt) {
        int k = i >> 6, o = i & 63;
        g_Wi2T[i] = Wi2[o * 128 + k];
    }
    for (int i = tid; i < 64 * 8; i += nt) {
        int h = i >> 3, d = i & 7;
        g_WrT[i] = Wr[d * 64 + h];
    }
}

// fast, accurate-enough transcendentals (abs err ~1e-6)
__device__ __forceinline__ float tanh_fast(float x) {
    float e = __expf(2.0f * x);
    return 1.0f - __fdividef(2.0f, 1.0f + e);
}
__device__ __forceinline__ float lipswish(float x) {
    return 0.909f * __fdividef(x, 1.0f + __expf(-x));
}

#define PACK_DUP(out, w) \
    asm("mov.b64 %0, {%1, %1};" : "=l"(out) : "r"(__float_as_uint(w)))
#define PACK2(out, lo, hi) \
    asm("mov.b64 %0, {%1, %2};" : "=l"(out) : "r"(__float_as_uint(lo)), "r"(__float_as_uint(hi)))
#define UNPACK2(lo, hi, in) \
    do { unsigned int _ul, _uh; \
         asm("mov.b64 {%0, %1}, %2;" : "=r"(_ul), "=r"(_uh) : "l"(in)); \
         lo = __uint_as_float(_ul); hi = __uint_as_float(_uh); } while (0)
#define FMA2(acc, w2, a2) \
    asm("fma.rn.f32x2 %0, %1, %2, %0;" : "+l"(acc) : "l"(w2), "l"(a2))

__global__ void __launch_bounds__(NTHR, 1) sde_kernel(
    const float* __restrict__ ts, const float* __restrict__ init_noise,
    const float* __restrict__ bm,
    const float* __restrict__ bi0, const float* __restrict__ bi1, const float* __restrict__ bi2,
    const float* __restrict__ scale_v, const float* __restrict__ bv2,
    const float* __restrict__ scale_c, const float* __restrict__ bc2,
    const float* __restrict__ br, float* __restrict__ out)
{
    __shared__ float  y_s   [BT][64];     // current state
    __shared__ float  ynew_s[BT][64];     // y + drift
    __shared__ float  h1_s  [16][256];    // [hv1 | hc1]  (padded rows 14,15)
    __shared__ float  h2v_s [16][128];    // drift-path hidden2 (v half only)
    __shared__ float4 h2q   [64][9];      // c-half hidden2, pair-packed:
                                          // h2q[kk][j] = {A[j][2kk],A[j+7][2kk],A[j][2kk+1],A[j+7][2kk+1]}
    __shared__ float  diff_s[64][17];     // diffusion increment, [h][b], padded
    __shared__ float2 bmp   [32][9];      // noise pairs: bmp[nz][j] = {bm[b=j], bm[b=j+7]}

    const int tid  = threadIdx.x;
    const int b0g  = blockIdx.x * BT;
    int nb = BATCH - b0g; if (nb > BT) nb = BT;
    const float ts0 = ts[0];

    // step-invariant per-thread parameters (hoisted out of the time loop)
    const int oB  = tid & 255;            // output index for phases B/C
    const int gB  = tid >> 8;             // batch-group for B/C
    const int o64 = tid & 63;             // output index for phase D
    const int gD  = tid >> 6;
    const float w0t_r = g_w0t[oB];
    const float b0_r  = g_b0[oB];
    const float b1_r  = g_b1[oB];
    const float bv2_r = bv2[o64];
    const float sv_r  = scale_v[o64];
    const int   n0    = tid << 2;         // phase-E column base
    const float4 sc4  = *(const float4*)&scale_c[n0];
    const float4 bcv4 = *(const float4*)&bc2[n0];

    // ---------------- initial MLP: init_noise -> y0 ----------------
    {
        float* nbuf = (float*)bmp;   // reuse as [14][32] staging
        for (int i = tid; i < BT * 32; i += NTHR) {
            int b = i >> 5, z = i & 31;
            nbuf[b * 32 + z] = (b < nb) ? init_noise[(size_t)(b0g + b) * INZ + z] : 0.0f;
        }
        __syncthreads();
        {   // L0: 32 -> 128, relu
            int o = tid & 127, g = tid >> 7;
            float acc[4];
            float bias = bi0[o];
            #pragma unroll
            for (int j = 0; j < 4; j++) acc[j] = bias;
            for (int k = 0; k < 32; k++) {
                float w = g_Wi0T[k * 128 + o];
                #pragma unroll
                for (int j = 0; j < 4; j++) acc[j] = fmaf(w, nbuf[(g * 4 + j) * 32 + k], acc[j]);
            }
            #pragma unroll
            for (int j = 0; j < 4; j++) h1_s[g * 4 + j][o] = fmaxf(acc[j], 0.0f);
        }
        __syncthreads();
        {   // L1: 128 -> 128, relu
            int o = tid & 127, g = tid >> 7;
            float acc[4];
            float bias = bi1[o];
            #pragma unroll
            for (int j = 0; j < 4; j++) acc[j] = bias;
            for (int k = 0; k < 128; k++) {
                float w = g_Wi1T[k * 128 + o];
                #pragma unroll
                for (int j = 0; j < 4; j++) acc[j] = fmaf(w, h1_s[g * 4 + j][k], acc[j]);
            }
            #pragma unroll
            for (int j = 0; j < 4; j++) h2v_s[g * 4 + j][o] = fmaxf(acc[j], 0.0f);
        }
        __syncthreads();
        {   // L2: 128 -> 64, identity -> y0
            int o = tid & 63, g = tid >> 6;
            float bias = bi2[o];
            float a0 = bias, a1 = bias;
            for (int k = 0; k < 128; k++) {
                float w = g_Wi2T[k * 64 + o];
                a0 = fmaf(w, h2v_s[g * 2 + 0][k], a0);
                a1 = fmaf(w, h2v_s[g * 2 + 1][k], a1);
            }
            if (g * 2 + 0 < BT) y_s[g * 2 + 0][o] = a0;
            if (g * 2 + 1 < BT) y_s[g * 2 + 1][o] = a1;
        }
        __syncthreads();
    }

    // ---------------- time scan ----------------
    for (int step = 0; step < STEPS; step++) {
        // stage noise for this step, pre-paired (b, b+7)
        for (int i = tid; i < BT * 32; i += NTHR) {
            int b = i >> 5, z = i & 31;
            float v = (b < nb)
                ? bm[(size_t)(b0g + b) * (STEPS * NZv) + step * NZv + z] : 0.0f;
            int j = (b < 7) ? b : b - 7;
            float* p = (float*)&bmp[z][j];
            p[(b < 7) ? 0 : 1] = v;
        }
        // ---- phase B: layer0 of v & c paths (256 outputs, K=65), k-paired f32x2 ----
        {
            const int bb = gB * 7;
            float tcur = ts0 + (float)step;
            float bias = fmaf(w0t_r, tcur, b0_r);
            unsigned long long acc2[7];
            #pragma unroll
            for (int j = 0; j < 7; j++) PACK2(acc2[j], bias, 0.0f);
            #pragma unroll 4
            for (int m = 0; m < 16; m++) {
                float4 w = g_W0P4[m * 256 + oB];
                unsigned long long wlo, whi;
                PACK2(wlo, w.x, w.y); PACK2(whi, w.z, w.w);
                #pragma unroll
                for (int j = 0; j < 7; j++) {
                    float4 a = *(const float4*)&y_s[bb + j][4 * m];
                    unsigned long long alo, ahi;
                    PACK2(alo, a.x, a.y); PACK2(ahi, a.z, a.w);
                    FMA2(acc2[j], wlo, alo);
                    FMA2(acc2[j], whi, ahi);
                }
            }
            #pragma unroll
            for (int j = 0; j < 7; j++) {
                float lo, hi; UNPACK2(lo, hi, acc2[j]);
                h1_s[bb + j][oB] = lipswish(lo + hi);
            }
        }
        __syncthreads();
        // ---- phase C: layer1 of v & c paths (256 outputs, K=128), k-paired f32x2 ----
        {
            const int bb = gB * 7;
            const int koff = (oB < 128) ? 0 : 128;
            unsigned long long acc2[7];
            #pragma unroll
            for (int j = 0; j < 7; j++) PACK2(acc2[j], b1_r, 0.0f);
            #pragma unroll 4
            for (int m = 0; m < 32; m++) {
                float4 w = g_W1P4[m * 256 + oB];
                unsigned long long wlo, whi;
                PACK2(wlo, w.x, w.y); PACK2(whi, w.z, w.w);
                #pragma unroll
                for (int j = 0; j < 7; j++) {
                    float4 a = *(const float4*)&h1_s[bb + j][koff + 4 * m];
                    unsigned long long alo, ahi;
                    PACK2(alo, a.x, a.y); PACK2(ahi, a.z, a.w);
                    FMA2(acc2[j], wlo, alo);
                    FMA2(acc2[j], whi, ahi);
                }
            }
            if (oB < 128) {
                #pragma unroll
                for (int j = 0; j < 7; j++) {
                    float lo, hi; UNPACK2(lo, hi, acc2[j]);
                    h2v_s[bb + j][oB] = lipswish(lo + hi);
                }
            } else {
                // pair-packed write for phase E: component c = 2*(k&1) + g
                int k = oB - 128, kk = k >> 1, c = ((k & 1) << 1) + gB;
                float* hq = (float*)h2q;
                #pragma unroll
                for (int j = 0; j < 7; j++) {
                    float lo, hi; UNPACK2(lo, hi, acc2[j]);
                    hq[(kk * 9 + j) * 4 + c] = lipswish(lo + hi);
                }
            }
        }
        __syncthreads();
        // ---- phase D: drift head (64 outputs, K=128), k-paired f32x2 ----
        {
            unsigned long long acc0, acc1;
            PACK2(acc0, bv2_r, 0.0f);
            PACK2(acc1, bv2_r, 0.0f);
            #pragma unroll 4
            for (int m = 0; m < 32; m++) {
                float4 w = g_Wv2P4[m * 64 + o64];
                unsigned long long wlo, whi;
                PACK2(wlo, w.x, w.y); PACK2(whi, w.z, w.w);
                float4 x0 = *(const float4*)&h2v_s[gD * 2 + 0][4 * m];
                float4 x1 = *(const float4*)&h2v_s[gD * 2 + 1][4 * m];
                unsigned long long a0lo, a0hi, a1lo, a1hi;
                PACK2(a0lo, x0.x, x0.y); PACK2(a0hi, x0.z, x0.w);
                PACK2(a1lo, x1.x, x1.y); PACK2(a1hi, x1.z, x1.w);
                FMA2(acc0, wlo, a0lo); FMA2(acc0, whi, a0hi);
                FMA2(acc1, wlo, a1lo); FMA2(acc1, whi, a1hi);
            }
            float l0, h0, l1, h1;
            UNPACK2(l0, h0, acc0);
            UNPACK2(l1, h1, acc1);
            int bb = gD * 2;
            if (bb + 0 < BT) ynew_s[bb + 0][o64] = y_s[bb + 0][o64] + sv_r * tanh_fast(l0 + h0);
            if (bb + 1 < BT) ynew_s[bb + 1][o64] = y_s[bb + 1][o64] + sv_r * tanh_fast(l1 + h1);
        }
        // ---- phase E: controlled field, 4 consecutive n per thread, f32x2 packed ----
        {
            unsigned long long acc2[4][7];
            #pragma unroll
            for (int ni = 0; ni < 4; ni++)
                #pragma unroll
                for (int j = 0; j < 7; j++) acc2[ni][j] = 0ULL;

            const float4* wb = ((const float4*)g_Wc2T) + tid;   // + k*512 per row
            float4 wA = __ldcg(&wb[0]);
            float4 wB = __ldcg(&wb[512]);
            #pragma unroll 1
            for (int kk = 0; kk < 64; kk++) {
                float4 nA, nB;
                if (kk < 63) {
                    nA = __ldcg(&wb[(size_t)(2 * kk + 2) * 512]);
                    nB = __ldcg(&wb[(size_t)(2 * kk + 3) * 512]);
                }
                unsigned long long wA2[4], wB2[4];
                PACK_DUP(wA2[0], wA.x); PACK_DUP(wA2[1], wA.y);
                PACK_DUP(wA2[2], wA.z); PACK_DUP(wA2[3], wA.w);
                PACK_DUP(wB2[0], wB.x); PACK_DUP(wB2[1], wB.y);
                PACK_DUP(wB2[2], wB.z); PACK_DUP(wB2[3], wB.w);
                #pragma unroll
                for (int j = 0; j < 7; j++) {
                    float4 a = h2q[kk][j];
                    unsigned long long alo, ahi;
                    PACK2(alo, a.x, a.y);
                    PACK2(ahi, a.z, a.w);
                    FMA2(acc2[0][j], wA2[0], alo); FMA2(acc2[0][j], wB2[0], ahi);
                    FMA2(acc2[1][j], wA2[1], alo); FMA2(acc2[1][j], wB2[1], ahi);
                    FMA2(acc2[2][j], wA2[2], alo); FMA2(acc2[2][j], wB2[2], ahi);
                    FMA2(acc2[3][j], wA2[3], alo); FMA2(acc2[3][j], wB2[3], ahi);
                }
                wA = nA; wB = nB;
            }
            // epilogue: bias + tanh + scale + noise, accumulate over the thread's 4 nz
            float2 s[7];
            #pragma unroll
            for (int j = 0; j < 7; j++) s[j] = make_float2(0.0f, 0.0f);
            const int nzb = (tid & 7) << 2;
            const float scs[4] = {sc4.x, sc4.y, sc4.z, sc4.w};
            const float bcs[4] = {bcv4.x, bcv4.y, bcv4.z, bcv4.w};
            #pragma unroll
            for (int ni = 0; ni < 4; ni++) {
                float sc = scs[ni];
                float bc = bcs[ni];
                #pragma unroll
                for (int j = 0; j < 7; j++) {
                    float z0, z1;
                    UNPACK2(z0, z1, acc2[ni][j]);
                    float t0 = sc * tanh_fast(z0 + bc);
                    float t1 = sc * tanh_fast(z1 + bc);
                    float2 bmv = bmp[nzb + ni][j];
                    s[j].x = fmaf(t0, bmv.x, s[j].x);
                    s[j].y = fmaf(t1, bmv.y, s[j].y);
                }
            }
            // reduce across the 8-lane group that shares h = tid>>3
            #pragma unroll
            for (int off = 1; off <= 4; off <<= 1) {
                #pragma unroll
                for (int j = 0; j < 7; j++) {
                    s[j].x += __shfl_xor_sync(0xffffffffu, s[j].x, off);
                    s[j].y += __shfl_xor_sync(0xffffffffu, s[j].y, off);
                }
            }
            if ((tid & 7) == 0) {
                int h = tid >> 3;
                #pragma unroll
                for (int j = 0; j < 7; j++) {
                    diff_s[h][j]     = s[j].x;
                    diff_s[h][j + 7] = s[j].y;
                }
            }
        }
        __syncthreads();
        // ---- phase F: y update ----
        for (int i = tid; i < BT * 64; i += NTHR) {
            int b = i >> 6, h = i & 63;
            y_s[b][h] = ynew_s[b][h] + diff_s[h][b];
        }
        __syncthreads();
        // ---- readout: out[b, step, :] = y @ Wr^T + br ----
        if (tid < BT * DOUT) {
            int b = tid >> 3, d = tid & 7;
            if (b < nb) {
                float acc = br[d];
                #pragma unroll 8
                for (int h = 0; h < 64; h++)
                    acc = fmaf(y_s[b][h], g_WrT[h * 8 + d], acc);
                out[(size_t)(b0g + b) * (STEPS * DOUT) + step * DOUT + d] = acc;
            }
        }
    }
}

extern "C" void kernel_launch(void* const* d_in, const int* in_sizes, int n_in,
                              void* d_out, int out_size) {
    (void)in_sizes; (void)n_in; (void)out_size;
    const float* ts         = (const float*)d_in[0];
    const float* init_noise = (const float*)d_in[1];
    const float* bm         = (const float*)d_in[2];
    const float* Wi0        = (const float*)d_in[3];
    const float* bi0        = (const float*)d_in[4];
    const float* Wi1        = (const float*)d_in[5];
    const float* bi1        = (const float*)d_in[6];
    const float* Wi2        = (const float*)d_in[7];
    const float* bi2        = (const float*)d_in[8];
    const float* scale_v    = (const float*)d_in[9];
    const float* Wv0        = (const float*)d_in[10];
    const float* bv0        = (const float*)d_in[11];
    const float* Wv1        = (const float*)d_in[12];
    const float* bv1        = (const float*)d_in[13];
    const float* Wv2        = (const float*)d_in[14];
    const float* bv2        = (const float*)d_in[15];
    const float* scale_c    = (const float*)d_in[16];
    const float* Wc0        = (const float*)d_in[17];
    const float* bc0        = (const float*)d_in[18];
    const float* Wc1        = (const float*)d_in[19];
    const float* bc1        = (const float*)d_in[20];
    const float* Wc2        = (const float*)d_in[21];
    const float* bc2        = (const float*)d_in[22];
    const float* Wr         = (const float*)d_in[23];
    const float* br         = (const float*)d_in[24];
    float* out = (float*)d_out;

    prep_kernel<<<256, 256>>>(Wi0, Wi1, Wi2, Wv0, bv0, Wv1, bv1, Wv2,
                              Wc0, bc0, Wc1, bc1, Wc2, Wr);
    sde_kernel<<<NCTA, NTHR>>>(ts, init_noise, bm, bi0, bi1, bi2,
                               scale_v, bv2, scale_c, bc2, br, out);
}

// round 7
// speedup vs baseline: 1.0573x; 1.0573x over previous
#include <cuda_runtime.h>
#include <math.h>

#define BATCH 2048
#define STEPS 64
#define HID   64
#define NZv   32
#define INZ   32
#define DOUT  8
#define BT    14
#define NTHR  512
#define NCTA  ((BATCH + BT - 1) / BT)   /* 147 */

// -------- pre-transposed weight scratch (filled by prep_kernel each call) ----
__device__ float4 g_W0P4 [16 * 256];  // [m][o]: Wx0[o][4m+1..4m+4] (x=v for o<128 else c)
__device__ float  g_w0t  [256];       // Wx0[o][0]  (the t column)
__device__ float4 g_W1P4 [32 * 256];  // [m][o]: Wx1[o][4m..4m+3]
__device__ float4 g_Wv2P4[32 * 64];   // [m][o]: Wv2[o][4m..4m+3]
__device__ float  g_Wc2T [128 * 2048];// [k][n]  (n contiguous -> LDG.128 per k)
__device__ float  g_Wi0T [32  * 128];
__device__ float  g_Wi1T [128 * 128];
__device__ float  g_Wi2T [128 * 64];
__device__ float  g_b0   [256];       // [bv0 | bc0]
__device__ float  g_b1   [256];       // [bv1 | bc1]
__device__ float  g_WrT  [64 * 8];    // WrT[h][d]

__global__ void prep_kernel(const float* __restrict__ Wi0, const float* __restrict__ Wi1,
                            const float* __restrict__ Wi2,
                            const float* __restrict__ Wv0, const float* __restrict__ bv0,
                            const float* __restrict__ Wv1, const float* __restrict__ bv1,
                            const float* __restrict__ Wv2,
                            const float* __restrict__ Wc0, const float* __restrict__ bc0,
                            const float* __restrict__ Wc1, const float* __restrict__ bc1,
                            const float* __restrict__ Wc2, const float* __restrict__ Wr) {
    int tid = blockIdx.x * blockDim.x + threadIdx.x;
    int nt  = gridDim.x * blockDim.x;
    for (int i = tid; i < 16 * 256; i += nt) {
        int m = i >> 8, o = i & 255;
        const float* row = (o < 128) ? &Wv0[o * 65] : &Wc0[(o - 128) * 65];
        g_W0P4[i] = make_float4(row[4 * m + 1], row[4 * m + 2], row[4 * m + 3], row[4 * m + 4]);
    }
    for (int o = tid; o < 256; o += nt) {
        const float* row = (o < 128) ? &Wv0[o * 65] : &Wc0[(o - 128) * 65];
        g_w0t[o] = row[0];
        g_b0[o] = (o < 128) ? bv0[o] : bc0[o - 128];
        g_b1[o] = (o < 128) ? bv1[o] : bc1[o - 128];
    }
    for (int i = tid; i < 32 * 256; i += nt) {
        int m = i >> 8, o = i & 255;
        const float* row = (o < 128) ? &Wv1[o * 128] : &Wc1[(o - 128) * 128];
        g_W1P4[i] = make_float4(row[4 * m], row[4 * m + 1], row[4 * m + 2], row[4 * m + 3]);
    }
    for (int i = tid; i < 32 * 64; i += nt) {
        int m = i >> 6, o = i & 63;
        const float* row = &Wv2[o * 128];
        g_Wv2P4[i] = make_float4(row[4 * m], row[4 * m + 1], row[4 * m + 2], row[4 * m + 3]);
    }
    for (int i = tid; i < 128 * 2048; i += nt) {
        int k = i >> 11, n = i & 2047;
        g_Wc2T[i] = Wc2[n * 128 + k];
    }
    for (int i = tid; i < 32 * 128; i += nt) {
        int k = i >> 7, o = i & 127;
        g_Wi0T[i] = Wi0[o * 32 + k];
    }
    for (int i = tid; i < 128 * 128; i += nt) {
        int k = i >> 7, o = i & 127;
        g_Wi1T[i] = Wi1[o * 128 + k];
    }
    for (int i = tid; i < 128 * 64; i += nt) {
        int k = i >> 6, o = i & 63;
        g_Wi2T[i] = Wi2[o * 128 + k];
    }
    for (int i = tid; i < 64 * 8; i += nt) {
        int h = i >> 3, d = i & 7;
        g_WrT[i] = Wr[d * 64 + h];
    }
}

// fast, accurate-enough transcendentals (abs err ~1e-6)
__device__ __forceinline__ float tanh_fast(float x) {
    float e = __expf(2.0f * x);
    return 1.0f - __fdividef(2.0f, 1.0f + e);
}
__device__ __forceinline__ float lipswish(float x) {
    return 0.909f * __fdividef(x, 1.0f + __expf(-x));
}

#define PACK_DUP(out, w) \
    asm("mov.b64 %0, {%1, %1};" : "=l"(out) : "r"(__float_as_uint(w)))
#define PACK2(out, lo, hi) \
    asm("mov.b64 %0, {%1, %2};" : "=l"(out) : "r"(__float_as_uint(lo)), "r"(__float_as_uint(hi)))
#define UNPACK2(lo, hi, in) \
    do { unsigned int _ul, _uh; \
         asm("mov.b64 {%0, %1}, %2;" : "=r"(_ul), "=r"(_uh) : "l"(in)); \
         lo = __uint_as_float(_ul); hi = __uint_as_float(_uh); } while (0)
#define FMA2(acc, w2, a2) \
    asm("fma.rn.f32x2 %0, %1, %2, %0;" : "+l"(acc) : "l"(w2), "l"(a2))

__global__ void __launch_bounds__(NTHR, 1) sde_kernel(
    const float* __restrict__ ts, const float* __restrict__ init_noise,
    const float* __restrict__ bm,
    const float* __restrict__ bi0, const float* __restrict__ bi1, const float* __restrict__ bi2,
    const float* __restrict__ scale_v, const float* __restrict__ bv2,
    const float* __restrict__ scale_c, const float* __restrict__ bc2,
    const float* __restrict__ br, float* __restrict__ out)
{
    __shared__ float  y_s   [BT][64];     // current state
    __shared__ float  ynew_s[BT][64];     // y + drift
    __shared__ float  h1_s  [16][256];    // [hv1 | hc1]  (padded rows 14,15)
    __shared__ float  h2v_s [16][128];    // drift-path hidden2 (v half only)
    __shared__ float4 h2q   [64][9];      // c-half hidden2, pair-packed:
                                          // h2q[kk][j] = {A[j][2kk],A[j+7][2kk],A[j][2kk+1],A[j+7][2kk+1]}
    __shared__ float  diff_s[64][17];     // diffusion increment, [h][b], padded
    __shared__ float2 bmp   [32][9];      // noise pairs: bmp[nz][j] = {bm[b=j], bm[b=j+7]}

    const int tid  = threadIdx.x;
    const int b0g  = blockIdx.x * BT;
    int nb = BATCH - b0g; if (nb > BT) nb = BT;
    const float ts0 = ts[0];

    // step-invariant per-thread parameters (hoisted out of the time loop)
    const int oB  = tid & 255;            // output index for phases B/C
    const int gB  = tid >> 8;             // batch-group for B/C
    const int o64 = tid & 63;             // output index for phase D
    const int gD  = tid >> 6;
    const float w0t_r = g_w0t[oB];
    const float b0_r  = g_b0[oB];
    const float b1_r  = g_b1[oB];
    const float bv2_r = bv2[o64];
    const float sv_r  = scale_v[o64];
    const int   n0    = tid << 2;         // phase-E column base
    const float4 sc4  = *(const float4*)&scale_c[n0];
    const float4 bcv4 = *(const float4*)&bc2[n0];

    // ---------------- initial MLP: init_noise -> y0 ----------------
    {
        float* nbuf = (float*)bmp;   // reuse as [14][32] staging
        for (int i = tid; i < BT * 32; i += NTHR) {
            int b = i >> 5, z = i & 31;
            nbuf[b * 32 + z] = (b < nb) ? init_noise[(size_t)(b0g + b) * INZ + z] : 0.0f;
        }
        __syncthreads();
        {   // L0: 32 -> 128, relu
            int o = tid & 127, g = tid >> 7;
            float acc[4];
            float bias = bi0[o];
            #pragma unroll
            for (int j = 0; j < 4; j++) acc[j] = bias;
            for (int k = 0; k < 32; k++) {
                float w = g_Wi0T[k * 128 + o];
                #pragma unroll
                for (int j = 0; j < 4; j++) acc[j] = fmaf(w, nbuf[(g * 4 + j) * 32 + k], acc[j]);
            }
            #pragma unroll
            for (int j = 0; j < 4; j++) h1_s[g * 4 + j][o] = fmaxf(acc[j], 0.0f);
        }
        __syncthreads();
        {   // L1: 128 -> 128, relu
            int o = tid & 127, g = tid >> 7;
            float acc[4];
            float bias = bi1[o];
            #pragma unroll
            for (int j = 0; j < 4; j++) acc[j] = bias;
            for (int k = 0; k < 128; k++) {
                float w = g_Wi1T[k * 128 + o];
                #pragma unroll
                for (int j = 0; j < 4; j++) acc[j] = fmaf(w, h1_s[g * 4 + j][k], acc[j]);
            }
            #pragma unroll
            for (int j = 0; j < 4; j++) h2v_s[g * 4 + j][o] = fmaxf(acc[j], 0.0f);
        }
        __syncthreads();
        {   // L2: 128 -> 64, identity -> y0
            int o = tid & 63, g = tid >> 6;
            float bias = bi2[o];
            float a0 = bias, a1 = bias;
            for (int k = 0; k < 128; k++) {
                float w = g_Wi2T[k * 64 + o];
                a0 = fmaf(w, h2v_s[g * 2 + 0][k], a0);
                a1 = fmaf(w, h2v_s[g * 2 + 1][k], a1);
            }
            if (g * 2 + 0 < BT) y_s[g * 2 + 0][o] = a0;
            if (g * 2 + 1 < BT) y_s[g * 2 + 1][o] = a1;
        }
        __syncthreads();
    }

    // ---------------- time scan ----------------
    for (int step = 0; step < STEPS; step++) {
        // stage noise for this step, pre-paired (b, b+7)
        for (int i = tid; i < BT * 32; i += NTHR) {
            int b = i >> 5, z = i & 31;
            float v = (b < nb)
                ? bm[(size_t)(b0g + b) * (STEPS * NZv) + step * NZv + z] : 0.0f;
            int j = (b < 7) ? b : b - 7;
            float* p = (float*)&bmp[z][j];
            p[(b < 7) ? 0 : 1] = v;
        }
        // ---- phase B: layer0 of v & c paths (256 outputs, K=65) ----
        // ulonglong2 loads: register-pair-aligned operands for fma.rn.f32x2, no movs
        {
            const int bb = gB * 7;
            float tcur = ts0 + (float)step;
            float bias = fmaf(w0t_r, tcur, b0_r);
            unsigned long long acc2[7];
            #pragma unroll
            for (int j = 0; j < 7; j++) PACK2(acc2[j], bias, 0.0f);
            const ulonglong2* wp = ((const ulonglong2*)g_W0P4) + oB;
            #pragma unroll 4
            for (int m = 0; m < 16; m++) {
                ulonglong2 w = wp[m * 256];
                #pragma unroll
                for (int j = 0; j < 7; j++) {
                    ulonglong2 a = *(const ulonglong2*)&y_s[bb + j][4 * m];
                    FMA2(acc2[j], w.x, a.x);
                    FMA2(acc2[j], w.y, a.y);
                }
            }
            #pragma unroll
            for (int j = 0; j < 7; j++) {
                float lo, hi; UNPACK2(lo, hi, acc2[j]);
                h1_s[bb + j][oB] = lipswish(lo + hi);
            }
        }
        __syncthreads();
        // ---- phase C: layer1 of v & c paths (256 outputs, K=128) ----
        {
            const int bb = gB * 7;
            const int koff = (oB < 128) ? 0 : 128;
            unsigned long long acc2[7];
            #pragma unroll
            for (int j = 0; j < 7; j++) PACK2(acc2[j], b1_r, 0.0f);
            const ulonglong2* wp = ((const ulonglong2*)g_W1P4) + oB;
            #pragma unroll 4
            for (int m = 0; m < 32; m++) {
                ulonglong2 w = wp[m * 256];
                #pragma unroll
                for (int j = 0; j < 7; j++) {
                    ulonglong2 a = *(const ulonglong2*)&h1_s[bb + j][koff + 4 * m];
                    FMA2(acc2[j], w.x, a.x);
                    FMA2(acc2[j], w.y, a.y);
                }
            }
            if (oB < 128) {
                #pragma unroll
                for (int j = 0; j < 7; j++) {
                    float lo, hi; UNPACK2(lo, hi, acc2[j]);
                    h2v_s[bb + j][oB] = lipswish(lo + hi);
                }
            } else {
                // pair-packed write for phase E: component c = 2*(k&1) + g
                int k = oB - 128, kk = k >> 1, c = ((k & 1) << 1) + gB;
                float* hq = (float*)h2q;
                #pragma unroll
                for (int j = 0; j < 7; j++) {
                    float lo, hi; UNPACK2(lo, hi, acc2[j]);
                    hq[(kk * 9 + j) * 4 + c] = lipswish(lo + hi);
                }
            }
        }
        __syncthreads();
        // ---- phase D: drift head (64 outputs, K=128) -> ynew = y + scale_v*tanh ----
        {
            unsigned long long acc0, acc1;
            PACK2(acc0, bv2_r, 0.0f);
            PACK2(acc1, bv2_r, 0.0f);
            const ulonglong2* wp = ((const ulonglong2*)g_Wv2P4) + o64;
            #pragma unroll 4
            for (int m = 0; m < 32; m++) {
                ulonglong2 w = wp[m * 64];
                ulonglong2 x0 = *(const ulonglong2*)&h2v_s[gD * 2 + 0][4 * m];
                ulonglong2 x1 = *(const ulonglong2*)&h2v_s[gD * 2 + 1][4 * m];
                FMA2(acc0, w.x, x0.x); FMA2(acc0, w.y, x0.y);
                FMA2(acc1, w.x, x1.x); FMA2(acc1, w.y, x1.y);
            }
            float l0, h0, l1, h1;
            UNPACK2(l0, h0, acc0);
            UNPACK2(l1, h1, acc1);
            int bb = gD * 2;
            if (bb + 0 < BT) ynew_s[bb + 0][o64] = y_s[bb + 0][o64] + sv_r * tanh_fast(l0 + h0);
            if (bb + 1 < BT) ynew_s[bb + 1][o64] = y_s[bb + 1][o64] + sv_r * tanh_fast(l1 + h1);
        }
        // ---- phase E: controlled field, 4 consecutive n per thread, f32x2 packed ----
        {
            unsigned long long acc2[4][7];
            #pragma unroll
            for (int ni = 0; ni < 4; ni++)
                #pragma unroll
                for (int j = 0; j < 7; j++) acc2[ni][j] = 0ULL;

            const float4* wb = ((const float4*)g_Wc2T) + tid;   // + k*512 per row
            float4 wA = __ldcg(&wb[0]);
            float4 wB = __ldcg(&wb[512]);
            #pragma unroll 1
            for (int kk = 0; kk < 64; kk++) {
                float4 nA, nB;
                if (kk < 63) {
                    nA = __ldcg(&wb[(size_t)(2 * kk + 2) * 512]);
                    nB = __ldcg(&wb[(size_t)(2 * kk + 3) * 512]);
                }
                unsigned long long wA2[4], wB2[4];
                PACK_DUP(wA2[0], wA.x); PACK_DUP(wA2[1], wA.y);
                PACK_DUP(wA2[2], wA.z); PACK_DUP(wA2[3], wA.w);
                PACK_DUP(wB2[0], wB.x); PACK_DUP(wB2[1], wB.y);
                PACK_DUP(wB2[2], wB.z); PACK_DUP(wB2[3], wB.w);
                #pragma unroll
                for (int j = 0; j < 7; j++) {
                    ulonglong2 a = *(const ulonglong2*)&h2q[kk][j];
                    FMA2(acc2[0][j], wA2[0], a.x); FMA2(acc2[0][j], wB2[0], a.y);
                    FMA2(acc2[1][j], wA2[1], a.x); FMA2(acc2[1][j], wB2[1], a.y);
                    FMA2(acc2[2][j], wA2[2], a.x); FMA2(acc2[2][j], wB2[2], a.y);
                    FMA2(acc2[3][j], wA2[3], a.x); FMA2(acc2[3][j], wB2[3], a.y);
                }
                wA = nA; wB = nB;
            }
            // epilogue: bias + tanh + scale + noise, accumulate over the thread's 4 nz
            float2 s[7];
            #pragma unroll
            for (int j = 0; j < 7; j++) s[j] = make_float2(0.0f, 0.0f);
            const int nzb = (tid & 7) << 2;
            const float scs[4] = {sc4.x, sc4.y, sc4.z, sc4.w};
            const float bcs[4] = {bcv4.x, bcv4.y, bcv4.z, bcv4.w};
            #pragma unroll
            for (int ni = 0; ni < 4; ni++) {
                float sc = scs[ni];
                float bc = bcs[ni];
                #pragma unroll
                for (int j = 0; j < 7; j++) {
                    float z0, z1;
                    UNPACK2(z0, z1, acc2[ni][j]);
                    float t0 = sc * tanh_fast(z0 + bc);
                    float t1 = sc * tanh_fast(z1 + bc);
                    float2 bmv = bmp[nzb + ni][j];
                    s[j].x = fmaf(t0, bmv.x, s[j].x);
                    s[j].y = fmaf(t1, bmv.y, s[j].y);
                }
            }
            // reduce across the 8-lane group that shares h = tid>>3
            #pragma unroll
            for (int off = 1; off <= 4; off <<= 1) {
                #pragma unroll
                for (int j = 0; j < 7; j++) {
                    s[j].x += __shfl_xor_sync(0xffffffffu, s[j].x, off);
                    s[j].y += __shfl_xor_sync(0xffffffffu, s[j].y, off);
                }
            }
            if ((tid & 7) == 0) {
                int h = tid >> 3;
                #pragma unroll
                for (int j = 0; j < 7; j++) {
                    diff_s[h][j]     = s[j].x;
                    diff_s[h][j + 7] = s[j].y;
                }
            }
        }
        __syncthreads();
        // ---- phase F: y update ----
        for (int i = tid; i < BT * 64; i += NTHR) {
            int b = i >> 6, h = i & 63;
            y_s[b][h] = ynew_s[b][h] + diff_s[h][b];
        }
        __syncthreads();
        // ---- readout: out[b, step, :] = y @ Wr^T + br ----
        if (tid < BT * DOUT) {
            int b = tid >> 3, d = tid & 7;
            if (b < nb) {
                float acc = br[d];
                #pragma unroll 8
                for (int h = 0; h < 64; h++)
                    acc = fmaf(y_s[b][h], g_WrT[h * 8 + d], acc);
                out[(size_t)(b0g + b) * (STEPS * DOUT) + step * DOUT + d] = acc;
            }
        }
    }
}

extern "C" void kernel_launch(void* const* d_in, const int* in_sizes, int n_in,
                              void* d_out, int out_size) {
    (void)in_sizes; (void)n_in; (void)out_size;
    const float* ts         = (const float*)d_in[0];
    const float* init_noise = (const float*)d_in[1];
    const float* bm         = (const float*)d_in[2];
    const float* Wi0        = (const float*)d_in[3];
    const float* bi0        = (const float*)d_in[4];
    const float* Wi1        = (const float*)d_in[5];
    const float* bi1        = (const float*)d_in[6];
    const float* Wi2        = (const float*)d_in[7];
    const float* bi2        = (const float*)d_in[8];
    const float* scale_v    = (const float*)d_in[9];
    const float* Wv0        = (const float*)d_in[10];
    const float* bv0        = (const float*)d_in[11];
    const float* Wv1        = (const float*)d_in[12];
    const float* bv1        = (const float*)d_in[13];
    const float* Wv2        = (const float*)d_in[14];
    const float* bv2        = (const float*)d_in[15];
    const float* scale_c    = (const float*)d_in[16];
    const float* Wc0        = (const float*)d_in[17];
    const float* bc0        = (const float*)d_in[18];
    const float* Wc1        = (const float*)d_in[19];
    const float* bc1        = (const float*)d_in[20];
    const float* Wc2        = (const float*)d_in[21];
    const float* bc2        = (const float*)d_in[22];
    const float* Wr         = (const float*)d_in[23];
    const float* br         = (const float*)d_in[24];
    float* out = (float*)d_out;

    prep_kernel<<<256, 256>>>(Wi0, Wi1, Wi2, Wv0, bv0, Wv1, bv1, Wv2,
                              Wc0, bc0, Wc1, bc1, Wc2, Wr);
    sde_kernel<<<NCTA, NTHR>>>(ts, init_noise, bm, bi0, bi1, bi2,
                               scale_v, bv2, scale_c, bc2, br, out);
}